// round 12
// baseline (speedup 1.0000x reference)
#include <cuda_runtime.h>
#include <cuda_bf16.h>
#include <cuda_fp16.h>
#include <math.h>
#include <stdint.h>

// Problem dims
#define B_  512
#define H_  1024
#define L_  256
#define V_  10000
#define H2_ 2048
#define H3_ 3072

// ---------------- scratch (device globals; no allocation) ----------------
__device__ float g_comb[B_ * H2_];
__device__ float g_attn_applied[B_ * H_];
__device__ float g_x[B_ * H_];
__device__ float g_gi[B_ * H3_];
__device__ float g_gh[B_ * H3_];
__device__ float g_part[4 * B_ * H_];   // split-K partials (8MB; holds 8*B*L too)

// ---------------- helpers ----------------
#define PACK_F32X2(d, lo, hi) \
    asm("mov.b64 %0, {%1, %2};" : "=l"(d) : "f"(lo), "f"(hi))
#define UNPACK_F32X2(lo, hi, v) \
    asm("mov.b64 {%0, %1}, %2;" : "=f"(lo), "=f"(hi) : "l"(v))
#define FMA_F32X2(d, a, b, c) \
    asm("fma.rn.f32x2 %0, %1, %2, %3;" : "=l"(d) : "l"(a), "l"(b), "l"(c))

__device__ __forceinline__ uint32_t packh2(float lo, float hi) {
    __half2 h = __floats2half2_rn(lo, hi);   // .x = lo (low 16 bits)
    return *reinterpret_cast<uint32_t*>(&h);
}

// ---------------- fused gather+concat ----------------
__global__ void concat_emb_kernel(const int* __restrict__ ids,
                                  const float* __restrict__ emb,
                                  const float* __restrict__ other) {
    int i = blockIdx.x * blockDim.x + threadIdx.x;
    int b = i >> 11;
    int j = i & (H2_ - 1);
    g_comb[i] = (j < H_) ? emb[(size_t)ids[b] * H_ + j]
                         : other[(size_t)b * H_ + (j - H_)];
}

// ==================== pipelined fp16 mma GEMM (fp32 accum) ====================
// C = A(M,K) @ W(K,N) (+bias). 512 thr = 16 warps (4m x 4n), BM=128 BN=128 BK=32.
// m16n8k16.f16, warp tile 32x32. smem packed half2 (2 k per u32).
// As [2][128][20] u32 (frag banks 4*gid+tig walk, conflict-free)
// Ws [2][16][136] u32 (stride 136 % 32 == 8 -> banks tig*8+gid, conflict-free)
struct GemmArgs {
    const float* A;
    const float* W;
    const float* bias;
    float* C;
};

template <bool ADDBIAS>
__device__ __forceinline__ void gemm_core(const float* __restrict__ A,
                                          const float* __restrict__ W,
                                          const float* __restrict__ bias,
                                          float* __restrict__ C,
                                          int N, int K, int kbeg, int kT) {
    __shared__ uint32_t As[2][128][20];   // 20480 B
    __shared__ uint32_t Ws[2][16][136];   // 17408 B  (37888 total, static)

    const int tid = threadIdx.x;
    const int lane = tid & 31;
    const int wid = tid >> 5;            // 0..15
    const int gid = lane >> 2;
    const int tig = lane & 3;
    const int warp_m = (wid & 3) * 32;
    const int warp_n = (wid >> 2) * 32;

    const int bm = blockIdx.y * 128;
    const int bn = blockIdx.x * 128;

    // A staging: row sa_r, k cols sa_c..sa_c+7 -> 4 packed u32
    const int sa_r = tid >> 2;           // 0..127
    const int sa_c = (tid & 3) * 8;      // 0,8,16,24
    const int sa_p = sa_c >> 1;          // pair col 0,4,8,12
    // W staging: k-pair row pk (k=2pk,2pk+1), n cols wc..wc+3
    const int pk = tid >> 5;             // 0..15
    const int wc = (lane) * 4;           // 0..124
    const int gnw = bn + wc;
    const bool wok = (gnw < N);

    const float* Ap = A + (size_t)(bm + sa_r) * K + kbeg + sa_c;
    const float* Wp0 = W + (size_t)(kbeg + 2 * pk) * N + gnw;
    const float* Wp1 = W + (size_t)(kbeg + 2 * pk + 1) * N + gnw;

    float acc[2][4][4];
#pragma unroll
    for (int mi = 0; mi < 2; mi++)
#pragma unroll
        for (int ni = 0; ni < 4; ni++)
#pragma unroll
            for (int r = 0; r < 4; r++) acc[mi][ni][r] = 0.f;

    float4 av0, av1;
    float4 wv0, wv1;

    auto LDG = [&](int t) {
        const float* ap = Ap + t * 32;
        av0 = *reinterpret_cast<const float4*>(ap);
        av1 = *reinterpret_cast<const float4*>(ap + 4);
        if (wok) {
            wv0 = *reinterpret_cast<const float4*>(Wp0 + (size_t)(t * 32) * N);
            wv1 = *reinterpret_cast<const float4*>(Wp1 + (size_t)(t * 32) * N);
        } else {
            wv0 = make_float4(0.f, 0.f, 0.f, 0.f);
            wv1 = wv0;
        }
    };

    auto STS = [&](int p) {
        uint4 ta;
        ta.x = packh2(av0.x, av0.y);
        ta.y = packh2(av0.z, av0.w);
        ta.z = packh2(av1.x, av1.y);
        ta.w = packh2(av1.z, av1.w);
        *reinterpret_cast<uint4*>(&As[p][sa_r][sa_p]) = ta;
        uint4 tw;
        tw.x = packh2(wv0.x, wv1.x);
        tw.y = packh2(wv0.y, wv1.y);
        tw.z = packh2(wv0.z, wv1.z);
        tw.w = packh2(wv0.w, wv1.w);
        *reinterpret_cast<uint4*>(&Ws[p][pk][wc]) = tw;
    };

    LDG(0);
    STS(0);
    __syncthreads();

    int p = 0;
    for (int t = 0; t < kT; t++) {
        if (t + 1 < kT) LDG(t + 1);

#pragma unroll
        for (int ks = 0; ks < 2; ks++) {       // two k=16 steps per 32-k tile
            const int kp = ks * 8;             // k-pair offset
            uint32_t af[2][4];
#pragma unroll
            for (int mi = 0; mi < 2; mi++) {
                int ar = warp_m + mi * 16 + gid;
                af[mi][0] = As[p][ar][kp + tig];
                af[mi][1] = As[p][ar + 8][kp + tig];
                af[mi][2] = As[p][ar][kp + tig + 4];
                af[mi][3] = As[p][ar + 8][kp + tig + 4];
            }
            uint32_t bf[4][2];
#pragma unroll
            for (int ni = 0; ni < 4; ni++) {
                int bc = warp_n + ni * 8 + gid;
                bf[ni][0] = Ws[p][kp + tig][bc];
                bf[ni][1] = Ws[p][kp + tig + 4][bc];
            }
#pragma unroll
            for (int mi = 0; mi < 2; mi++)
#pragma unroll
                for (int ni = 0; ni < 4; ni++) {
                    asm volatile(
                        "mma.sync.aligned.m16n8k16.row.col.f32.f16.f16.f32 "
                        "{%0,%1,%2,%3}, {%4,%5,%6,%7}, {%8,%9}, {%0,%1,%2,%3};\n"
                        : "+f"(acc[mi][ni][0]), "+f"(acc[mi][ni][1]),
                          "+f"(acc[mi][ni][2]), "+f"(acc[mi][ni][3])
                        : "r"(af[mi][0]), "r"(af[mi][1]),
                          "r"(af[mi][2]), "r"(af[mi][3]),
                          "r"(bf[ni][0]), "r"(bf[ni][1]));
                }
        }

        if (t + 1 < kT) STS(p ^ 1);
        __syncthreads();
        p ^= 1;
    }

    // epilogue
#pragma unroll
    for (int mi = 0; mi < 2; mi++) {
        int r0 = bm + warp_m + mi * 16 + gid;
#pragma unroll
        for (int ni = 0; ni < 4; ni++) {
            int c0 = bn + warp_n + ni * 8 + 2 * tig;
            if (c0 < N) {
                float v0 = acc[mi][ni][0], v1 = acc[mi][ni][1];
                float v2 = acc[mi][ni][2], v3 = acc[mi][ni][3];
                if (ADDBIAS) {
                    float bz0 = bias[c0];
                    float bz1 = (c0 + 1 < N) ? bias[c0 + 1] : 0.f;
                    v0 += bz0; v1 += bz1; v2 += bz0; v3 += bz1;
                }
                C[(size_t)r0 * N + c0] = v0;
                C[(size_t)(r0 + 8) * N + c0] = v2;
                if (c0 + 1 < N) {
                    C[(size_t)r0 * N + c0 + 1] = v1;
                    C[(size_t)(r0 + 8) * N + c0 + 1] = v3;
                }
            }
        }
    }
}

// MODE: 0 = plain (full K, bias), 1 = split-K (z = k-chunk, raw partials),
//       2 = dual (z selects arg set, full K, bias)
template <int MODE>
__global__ void __launch_bounds__(512)
gemm_h16p(GemmArgs g0, GemmArgs g1, int M, int N, int K, int kLen) {
    const GemmArgs ga = (MODE == 2 && blockIdx.z == 1) ? g1 : g0;
    const int kbeg = (MODE == 1) ? blockIdx.z * kLen : 0;
    const int kT = ((MODE == 1) ? kLen : K) / 32;
    float* C = ga.C + ((MODE == 1) ? (size_t)blockIdx.z * M * N : 0);
    if (MODE == 1)
        gemm_core<false>(ga.A, ga.W, ga.bias, C, N, K, kbeg, kT);
    else
        gemm_core<true>(ga.A, ga.W, ga.bias, C, N, K, kbeg, kT);
}

// ---------------- exact-fp32 FFMA2 GEMM (attn logits only) ----------------
__global__ void gemm_f32x2_split_kernel(const float* __restrict__ A,
                                        const float* __restrict__ W,
                                        float* __restrict__ C,
                                        int M, int N, int K, int kLen) {
    __shared__ float As[16][128];
    __shared__ float Ws[16][68];

    const int tid = threadIdx.x;
    const int bm = blockIdx.y * 128;
    const int bn = blockIdx.x * 64;
    const int tm = (tid >> 4) * 8;
    const int tn = (tid & 15) * 4;

    const int am = tid >> 1;
    const int ak = (tid & 1) * 8;
    const float* Ap = A + (size_t)(bm + am) * K + ak;
    const int wk = tid >> 4;
    const int wn = (tid & 15) * 4;
    const int gnw = bn + wn;
    const float* Wp = W + (size_t)wk * N + gnw;

    unsigned long long acc[4][4];
#pragma unroll
    for (int i = 0; i < 4; i++)
#pragma unroll
        for (int j = 0; j < 4; j++) acc[i][j] = 0ULL;

    const int kbeg = blockIdx.z * kLen;
    const int kend = kbeg + kLen;

    for (int k0 = kbeg; k0 < kend; k0 += 16) {
        float4 av0 = *reinterpret_cast<const float4*>(Ap + k0);
        float4 av1 = *reinterpret_cast<const float4*>(Ap + k0 + 4);
        float4 wv = make_float4(0.f, 0.f, 0.f, 0.f);
        if (gnw < N)
            wv = *reinterpret_cast<const float4*>(Wp + (size_t)k0 * N);

        __syncthreads();
        As[ak + 0][am] = av0.x; As[ak + 1][am] = av0.y;
        As[ak + 2][am] = av0.z; As[ak + 3][am] = av0.w;
        As[ak + 4][am] = av1.x; As[ak + 5][am] = av1.y;
        As[ak + 6][am] = av1.z; As[ak + 7][am] = av1.w;
        *reinterpret_cast<float4*>(&Ws[wk][wn]) = wv;
        __syncthreads();

#pragma unroll
        for (int k = 0; k < 16; k++) {
            float4 a0 = *reinterpret_cast<const float4*>(&As[k][tm]);
            float4 a1 = *reinterpret_cast<const float4*>(&As[k][tm + 4]);
            float4 w  = *reinterpret_cast<const float4*>(&Ws[k][tn]);
            unsigned long long ap[4], wb[4];
            PACK_F32X2(ap[0], a0.x, a0.y);
            PACK_F32X2(ap[1], a0.z, a0.w);
            PACK_F32X2(ap[2], a1.x, a1.y);
            PACK_F32X2(ap[3], a1.z, a1.w);
            PACK_F32X2(wb[0], w.x, w.x);
            PACK_F32X2(wb[1], w.y, w.y);
            PACK_F32X2(wb[2], w.z, w.z);
            PACK_F32X2(wb[3], w.w, w.w);
#pragma unroll
            for (int i = 0; i < 4; i++)
#pragma unroll
                for (int j = 0; j < 4; j++)
                    FMA_F32X2(acc[i][j], ap[i], wb[j], acc[i][j]);
        }
    }

    float* Cb = C + (size_t)blockIdx.z * M * N;
#pragma unroll
    for (int i = 0; i < 4; i++) {
        int r0 = bm + tm + 2 * i;
#pragma unroll
        for (int j = 0; j < 4; j++) {
            int c = bn + tn + j;
            if (c < N) {
                float lo, hi;
                UNPACK_F32X2(lo, hi, acc[i][j]);
                Cb[(size_t)r0 * N + c] = lo;
                Cb[(size_t)(r0 + 1) * N + c] = hi;
            }
        }
    }
}

// ---------------- softmax (attn) ----------------
__global__ void softmax_attn_kernel(const float* __restrict__ attn_b,
                                    float* __restrict__ out) {
    int b = blockIdx.x;
    int t = threadIdx.x;
    float v = attn_b[t];
#pragma unroll
    for (int s = 0; s < 8; s++)
        v += g_part[(size_t)s * B_ * L_ + b * L_ + t];
    __shared__ float red[256];
    red[t] = v;
    __syncthreads();
    for (int s = 128; s; s >>= 1) {
        if (t < s) red[t] = fmaxf(red[t], red[t + s]);
        __syncthreads();
    }
    float m = red[0];
    __syncthreads();
    float e = expf(v - m);
    red[t] = e;
    __syncthreads();
    for (int s = 128; s; s >>= 1) {
        if (t < s) red[t] += red[t + s];
        __syncthreads();
    }
    out[b * L_ + t] = e / red[0];
}

// ---------------- reduce 4 K-partials + bias + relu -> g_x ----------------
__global__ void reduce_relu_kernel(const float* __restrict__ bias) {
    int i = blockIdx.x * blockDim.x + threadIdx.x;
    int j = i & (H_ - 1);
    float v = g_part[i] + g_part[B_ * H_ + i] + g_part[2 * B_ * H_ + i]
            + g_part[3 * B_ * H_ + i] + bias[j];
    g_x[i] = fmaxf(v, 0.f);
}

// ---------------- attn_applied ----------------
__global__ void attn_apply_kernel(const float* __restrict__ attw,
                                  const float* __restrict__ enc) {
    int b = blockIdx.y;
    int hc = blockIdx.x;
    int t = threadIdx.x;
    __shared__ float w[L_];
    w[t] = attw[b * L_ + t];
    __syncthreads();
    int h = hc * 256 + t;
    const float* e = enc + (size_t)b * L_ * H_ + h;
    float acc = 0.f;
#pragma unroll 8
    for (int l = 0; l < L_; l++)
        acc += w[l] * e[(size_t)l * H_];
    g_attn_applied[(size_t)b * H_ + h] = acc;
}

// ---------------- GRU elementwise ----------------
__global__ void gru_kernel(const float* __restrict__ h,
                           float* __restrict__ new_h) {
    int i = blockIdx.x * blockDim.x + threadIdx.x;
    int b = i >> 10;
    int j = i & (H_ - 1);
    const float* gib = g_gi + (size_t)b * H3_;
    const float* ghb = g_gh + (size_t)b * H3_;
    float r = 1.f / (1.f + expf(-(gib[j] + ghb[j])));
    float z = 1.f / (1.f + expf(-(gib[H_ + j] + ghb[H_ + j])));
    float n = tanhf(gib[2 * H_ + j] + r * ghb[2 * H_ + j]);
    new_h[i] = (1.f - z) * n + z * h[i];
}

// ---------------- log_softmax ----------------
__global__ void logsoftmax_kernel(float* __restrict__ x) {
    int b = blockIdx.x;
    int t = threadIdx.x;
    float* row = x + (size_t)b * V_;
    __shared__ float red[256];
    float m = -1e30f;
    for (int i = t; i < V_; i += 256) m = fmaxf(m, row[i]);
    red[t] = m;
    __syncthreads();
    for (int s = 128; s; s >>= 1) {
        if (t < s) red[t] = fmaxf(red[t], red[t + s]);
        __syncthreads();
    }
    m = red[0];
    __syncthreads();
    float sum = 0.f;
    for (int i = t; i < V_; i += 256) sum += expf(row[i] - m);
    red[t] = sum;
    __syncthreads();
    for (int s = 128; s; s >>= 1) {
        if (t < s) red[t] += red[t + s];
        __syncthreads();
    }
    float lse = m + logf(red[0]);
    for (int i = t; i < V_; i += 256) row[i] -= lse;
}

// ---------------- launch ----------------
extern "C" void kernel_launch(void* const* d_in, const int* in_sizes, int n_in,
                              void* d_out, int out_size) {
    const int*   input_ids = (const int*)d_in[0];
    const float* hidden    = (const float*)d_in[1];
    const float* enc       = (const float*)d_in[2];
    const float* emb       = (const float*)d_in[3];
    const float* attn_w    = (const float*)d_in[4];
    const float* attn_b    = (const float*)d_in[5];
    const float* comb_w    = (const float*)d_in[6];
    const float* comb_b    = (const float*)d_in[7];
    const float* w_ih      = (const float*)d_in[8];
    const float* w_hh      = (const float*)d_in[9];
    const float* b_ih      = (const float*)d_in[10];
    const float* b_hh      = (const float*)d_in[11];
    const float* out_w     = (const float*)d_in[12];
    const float* out_b     = (const float*)d_in[13];

    float* out       = (float*)d_out;
    float* new_h_out = out + (size_t)B_ * V_;
    float* attw_out  = new_h_out + (size_t)B_ * H_;

    float *p_comb, *p_app, *p_x, *p_gi, *p_gh, *p_part;
    cudaGetSymbolAddress((void**)&p_comb, g_comb);
    cudaGetSymbolAddress((void**)&p_app,  g_attn_applied);
    cudaGetSymbolAddress((void**)&p_x,    g_x);
    cudaGetSymbolAddress((void**)&p_gi,   g_gi);
    cudaGetSymbolAddress((void**)&p_gh,   g_gh);
    cudaGetSymbolAddress((void**)&p_part, g_part);

    GemmArgs none = {nullptr, nullptr, nullptr, nullptr};

    // 1. g_comb = [emb[ids] | hidden]
    concat_emb_kernel<<<(B_ * H2_) / 256, 256>>>(input_ids, emb, hidden);
    // 2. attn logits, exact fp32, split-K=8 -> partials
    {
        dim3 g(L_ / 64, B_ / 128, 8);
        gemm_f32x2_split_kernel<<<g, 256>>>(p_comb, attn_w, p_part,
                                            B_, L_, H2_, H2_ / 8);
    }
    // 3. reduce + softmax -> attw_out
    softmax_attn_kernel<<<B_, 256>>>(attn_b, attw_out);
    // 4. attn_applied
    {
        dim3 g(H_ / 256, B_);
        attn_apply_kernel<<<g, 256>>>(attw_out, enc);
    }
    // 5. g_comb = [emb[ids] | attn_applied]
    concat_emb_kernel<<<(B_ * H2_) / 256, 256>>>(input_ids, emb, p_app);
    // 6. comb GEMM (fp16 mma, BN=128), split-K=4 -> partials
    {
        dim3 g(H_ / 128, B_ / 128, 4);
        GemmArgs a0 = {p_comb, comb_w, nullptr, p_part};
        gemm_h16p<1><<<g, 512>>>(a0, none, B_, H_, H2_, H2_ / 4);
    }
    // 7. x = relu(sum partials + bias)
    reduce_relu_kernel<<<(B_ * H_) / 256, 256>>>(comb_b);
    // 8. gi = x@w_ih+b_ih ; gh = hidden@w_hh+b_hh (dual via grid.z)
    {
        dim3 g(H3_ / 128, B_ / 128, 2);
        GemmArgs a0 = {p_x,    w_ih, b_ih, p_gi};
        GemmArgs a1 = {hidden, w_hh, b_hh, p_gh};
        gemm_h16p<2><<<g, 512>>>(a0, a1, B_, H3_, H_, H_);
    }
    // 9. GRU -> new_hidden
    gru_kernel<<<(B_ * H_) / 256, 256>>>(hidden, new_h_out);
    // 10. out-proj (fp16 mma, BN=128)
    {
        dim3 g((V_ + 127) / 128, B_ / 128, 1);
        GemmArgs a0 = {new_h_out, out_w, out_b, out};
        gemm_h16p<0><<<g, 512>>>(a0, none, B_, V_, H_, H_);
    }
    // 11. log_softmax
    logsoftmax_kernel<<<B_, 256>>>(out);
}